// round 11
// baseline (speedup 1.0000x reference)
#include <cuda_runtime.h>
#include <cuda_fp16.h>
#include <cstdint>
#include <cfloat>

#define N_VEC  16384
#define VOCAB  4096
#define C_DIM  256

// rigorous fp16-quantization margin: |s_hat - s_exact| <= MCOEF*||x||*||e|| + SLK
#define MCOEF  1.06e-3f
#define SLK    0.05f

// ---------------------------------------------------------------------------
__device__ float  g_hflat[N_VEC * C_DIM];     // h transposed (N,C) fp32
__device__ __half g_A16[N_VEC * C_DIM];       // fp16 copy
__device__ __half g_B16[VOCAB * C_DIM];       // fp16 codebook
__device__ float  g_halfnorm[VOCAB];          // 0.5*||e||^2 (rescore/loss)
__device__ alignas(16) float2 g_hne[VOCAB];   // (0.5*||e||^2, ||e||) packed
__device__ float  g_xnorm[N_VEC];             // ||x||
__device__ float  g_bestscore[N_VEC];
__device__ int    g_bestidx[N_VEC];
__device__ float  g_partial[4096];

// ---------------------------------------------------------------------------
__device__ __forceinline__ uint32_t smem_u32(const void* p) {
    uint32_t a;
    asm("{ .reg .u64 t; cvta.to.shared.u64 t, %1; cvt.u32.u64 %0, t; }"
        : "=r"(a) : "l"(p));
    return a;
}
__device__ __forceinline__ unsigned fmap(float f) {
    unsigned u = __float_as_uint(f);
    return u ^ ((unsigned)((int)u >> 31) | 0x80000000u);
}
#define CP_ASYNC16(saddr, gptr) \
    asm volatile("cp.async.cg.shared.global [%0], [%1], 16;" \
                 :: "r"(saddr), "l"(gptr) : "memory")
#define CP_COMMIT() asm volatile("cp.async.commit_group;" ::: "memory")
#define CP_WAIT1()  asm volatile("cp.async.wait_group 1;" ::: "memory")
#define CP_WAIT0()  asm volatile("cp.async.wait_group 0;" ::: "memory")

#define MMA16816(c, a, b) \
    asm volatile( \
        "mma.sync.aligned.m16n8k16.row.col.f32.f16.f16.f32 " \
        "{%0,%1,%2,%3}, {%4,%5,%6,%7}, {%8,%9}, {%0,%1,%2,%3};" \
        : "+f"((c)[0]), "+f"((c)[1]), "+f"((c)[2]), "+f"((c)[3]) \
        : "r"((a)[0]), "r"((a)[1]), "r"((a)[2]), "r"((a)[3]), \
          "r"((b)[0]), "r"((b)[1]))

#define LDSM_X4(r0, r1, r2, r3, addr) \
    asm volatile("ldmatrix.sync.aligned.m8n8.x4.shared.b16 {%0,%1,%2,%3}, [%4];" \
                 : "=r"(r0), "=r"(r1), "=r"(r2), "=r"(r3) : "r"(addr))

// ---------------------------------------------------------------------------
// transpose h (B,C,H,W)->(N,C): fp32 + fp16 copies, fused sum(h^2) partial
__global__ void prep_h_kernel(const float* __restrict__ h) {
    __shared__ float tile[32][33];
    __shared__ float rsm[8];
    int b = blockIdx.z, ct = blockIdx.y, st = blockIdx.x;
    int c0 = ct * 32, s0 = st * 32;
    int tx = threadIdx.x, ty = threadIdx.y;
    int t = ty * 32 + tx;

    const float* src = h + ((size_t)b * C_DIM + c0) * 1024 + s0;
    float sq = 0.f;
    #pragma unroll
    for (int i = 0; i < 32; i += 8) {
        float v = src[(size_t)(ty + i) * 1024 + tx];
        tile[ty + i][tx] = v;
        sq = fmaf(v, v, sq);
    }
    __syncthreads();
    size_t rowbase = (size_t)b * 1024 + s0;
    #pragma unroll
    for (int i = 0; i < 32; i += 8) {
        float x = tile[tx][ty + i];
        size_t idx = (rowbase + ty + i) * C_DIM + c0 + tx;
        g_hflat[idx] = x;
        g_A16[idx]   = __float2half_rn(x);
    }
    #pragma unroll
    for (int o = 16; o > 0; o >>= 1) sq += __shfl_down_sync(0xFFFFFFFFu, sq, o);
    if ((t & 31) == 0) rsm[t >> 5] = sq;
    __syncthreads();
    if (t == 0) {
        float tot = 0.f;
        #pragma unroll
        for (int i = 0; i < 8; i++) tot += rsm[i];
        g_partial[(b * 8 + ct) * 32 + st] = tot;
    }
}

__global__ void prep_emb_kernel(const float* __restrict__ emb) {
    int v = blockIdx.x, t = threadIdx.x;
    float x = emb[v * C_DIM + t];
    g_B16[v * C_DIM + t] = __float2half_rn(x);

    float s = x * x;
    __shared__ float sm[8];
    #pragma unroll
    for (int o = 16; o > 0; o >>= 1) s += __shfl_down_sync(0xFFFFFFFFu, s, o);
    if ((t & 31) == 0) sm[t >> 5] = s;
    __syncthreads();
    if (t == 0) {
        float tot = 0.f;
        #pragma unroll
        for (int i = 0; i < 8; i++) tot += sm[i];
        g_halfnorm[v] = 0.5f * tot;
        g_hne[v] = make_float2(0.5f * tot, sqrtf(tot));
    }
}

__global__ void xnorm_kernel() {
    int w = threadIdx.x >> 5, lane = threadIdx.x & 31;
    int r = blockIdx.x * 8 + w;
    const float* xr = g_hflat + (size_t)r * C_DIM;
    float p = 0.f;
    #pragma unroll
    for (int i = 0; i < 8; i++) { float x = xr[lane + i * 32]; p = fmaf(x, x, p); }
    #pragma unroll
    for (int o = 16; o > 0; o >>= 1) p += __shfl_xor_sync(0xFFFFFFFFu, p, o);
    if (lane == 0) g_xnorm[r] = sqrtf(p);
}

// ---------------------------------------------------------------------------
// Fused GEMM with A entirely in registers (loaded once), B full-K smem tiles,
// 2-stage cp.async, register filter + exact rescore.
// 128 CTAs (M tile 128) x 256 threads; 8 warps: wm in {0..3} x wn in {0,1};
// warp tile 32x64. v-tile N=128 (32 tiles), full K=256 per B stage.
#define MTILE 128
#define LDS   264                  // halfs: row 528B == 16 mod 128 (LDSM ok)
#define BSTG  (128 * LDS * 2)      // 67584 bytes per B stage
#define CAP   32
#define OFF_B0   0
#define OFF_B1   67584
#define OFF_HNE  135168            // 4 slots * 128 float2 = 4096
#define OFF_XN   139264            // 128 floats
#define OFF_ML   139776            // 128 u32
#define OFF_CNT  140288            // 128 ints
#define OFF_CAND 140800            // 128*32 u16 = 8192
#define SMEM_P1  148992

__global__ __launch_bounds__(256, 1) void pass1_kernel(const float* __restrict__ emb) {
    extern __shared__ char smem[];
    const uint32_t sb = smem_u32(smem);
    float*    XN  = reinterpret_cast<float*>(smem + OFF_XN);
    unsigned* ML  = reinterpret_cast<unsigned*>(smem + OFF_ML);
    int*      CNT = reinterpret_cast<int*>(smem + OFF_CNT);
    unsigned short* CAND = reinterpret_cast<unsigned short*>(smem + OFF_CAND);

    const int tid = threadIdx.x;
    const int w = tid >> 5, lane = tid & 31;
    const int wm = w & 3, wn = w >> 2;
    const int m0 = blockIdx.x * MTILE;
    const int lg = lane >> 2;        // group id 0..7
    const int lq = lane & 3;         // quad id 0..3

    if (tid < 128) {
        XN[tid] = __ldg(&g_xnorm[m0 + tid]);
        ML[tid] = 0u;
        CNT[tid] = 0;
    }

    // ldmatrix lane addresses (bytes)
    const uint32_t aLane = (uint32_t)(((lane & 15) * LDS + (lane >> 4) * 8) * 2);
    const uint32_t bLane = (uint32_t)(
        ((((lane & 7) | ((lane >> 4) << 3)) * LDS) + ((lane >> 3) & 1) * 8) * 2);
    const uint32_t bWarp = (uint32_t)(wn * 64 * LDS * 2) + bLane;

    // tile loader mapping: row = tid>>1 (0..127), half = tid&1 (128 cols each)
    const int lbr = tid >> 1, lbh = tid & 1;

    // ---- stage A tile into B0 region, extract fragments, then free it ----
    {
        const __half* asrc = g_A16 + (size_t)m0 * C_DIM;
        #pragma unroll
        for (int j = 0; j < 16; j++) {
            CP_ASYNC16(sb + OFF_B0 + (uint32_t)((lbr * LDS + lbh * 128 + j * 8) * 2),
                       asrc + (size_t)lbr * C_DIM + lbh * 128 + j * 8);
        }
        CP_COMMIT();
        CP_WAIT0();
        __syncthreads();
    }

    uint32_t a[16][2][4];            // A fragments for full K=256 (128 regs)
    {
        const uint32_t aBase = sb + OFF_B0 + (uint32_t)(wm * 32 * LDS * 2) + aLane;
        #pragma unroll
        for (int ks = 0; ks < 16; ks++) {
            LDSM_X4(a[ks][0][0], a[ks][0][1], a[ks][0][2], a[ks][0][3],
                    aBase + (uint32_t)(ks * 32));
            LDSM_X4(a[ks][1][0], a[ks][1][1], a[ks][1][2], a[ks][1][3],
                    aBase + (uint32_t)(16 * LDS * 2 + ks * 32));
        }
    }
    __syncthreads();   // all A fragment reads done before B0 overwrites

    // prefetch B v-tile v into stage v&1 + its (halfnorm,||e||) into slot v&3
    #define PREFETCH(v) do {                                                    \
        const uint32_t _dst = sb + (((v) & 1) ? OFF_B1 : OFF_B0);               \
        const __half* _src = g_B16 + (size_t)(v) * 128 * C_DIM;                 \
        _Pragma("unroll")                                                       \
        for (int _j = 0; _j < 16; _j++) {                                       \
            CP_ASYNC16(_dst + (uint32_t)((lbr * LDS + lbh * 128 + _j * 8) * 2), \
                       _src + (size_t)lbr * C_DIM + lbh * 128 + _j * 8);        \
        }                                                                       \
        if (tid < 64) {                                                         \
            CP_ASYNC16(sb + OFF_HNE + (uint32_t)(((v) & 3) * 1024 + tid * 16),  \
                       reinterpret_cast<const float*>(g_hne) + (v) * 256 + tid * 4); \
        }                                                                       \
        CP_COMMIT();                                                            \
    } while (0)

    PREFETCH(0);
    PREFETCH(1);

    float acc[2][8][4];
    #pragma unroll
    for (int mf = 0; mf < 2; mf++)
        #pragma unroll
        for (int nf = 0; nf < 8; nf++)
            #pragma unroll
            for (int q = 0; q < 4; q++) acc[mf][nf][q] = 0.f;

    #pragma unroll 1
    for (int vt = 0; vt < 32; vt++) {
        if (vt < 31) CP_WAIT1(); else CP_WAIT0();
        __syncthreads();             // stage vt&1 visible to all warps

        const uint32_t bStage = sb + ((vt & 1) ? OFF_B1 : OFF_B0) + bWarp;

        #pragma unroll
        for (int ks = 0; ks < 16; ks++) {
            uint32_t b[8][2];
            const uint32_t kb = (uint32_t)(ks * 32);
            LDSM_X4(b[0][0], b[0][1], b[1][0], b[1][1], bStage + kb);
            LDSM_X4(b[2][0], b[2][1], b[3][0], b[3][1],
                    bStage + (uint32_t)(16 * LDS * 2) + kb);
            LDSM_X4(b[4][0], b[4][1], b[5][0], b[5][1],
                    bStage + (uint32_t)(32 * LDS * 2) + kb);
            LDSM_X4(b[6][0], b[6][1], b[7][0], b[7][1],
                    bStage + (uint32_t)(48 * LDS * 2) + kb);
            #pragma unroll
            for (int mf = 0; mf < 2; mf++)
                #pragma unroll
                for (int nf = 0; nf < 8; nf++)
                    MMA16816(acc[mf][nf], a[ks][mf], b[nf]);
        }
        __syncthreads();             // all B reads done before refill

        if (vt + 2 < 32) PREFETCH(vt + 2);

        // ---- register epilogue for v-tile [vt*128, +128) ----
        const float* HNE = reinterpret_cast<const float*>(
            smem + OFF_HNE + (vt & 3) * 1024);
        const int v0 = vt << 7;
        const int rbase = wm * 32 + lg;
        #pragma unroll
        for (int mf = 0; mf < 2; mf++) {
            #pragma unroll
            for (int hh = 0; hh < 2; hh++) {
                const int row = rbase + mf * 16 + hh * 8;
                const float mx = MCOEF * XN[row];
                float lowmax = -FLT_MAX;
                float ub[8][2];
                #pragma unroll
                for (int nf = 0; nf < 8; nf++) {
                    const int col = wn * 64 + nf * 8 + lq * 2;
                    float4 q4 = *reinterpret_cast<const float4*>(HNE + col * 2);
                    float s0 = acc[mf][nf][2 * hh]     - q4.x;
                    float s1 = acc[mf][nf][2 * hh + 1] - q4.z;
                    float me0 = fmaf(mx, q4.y, SLK);
                    float me1 = fmaf(mx, q4.w, SLK);
                    lowmax = fmaxf(lowmax, fmaxf(s0 - me0, s1 - me1));
                    ub[nf][0] = s0 + me0;
                    ub[nf][1] = s1 + me1;
                }
                atomicMax(&ML[row], fmap(lowmax));
                // stale-lower threshold is still a valid lower bound ->
                // candidate set stays a superset of the true argmax
                const unsigned thr = ML[row];
                #pragma unroll
                for (int nf = 0; nf < 8; nf++) {
                    const int col = v0 + wn * 64 + nf * 8 + lq * 2;
                    if (fmap(ub[nf][0]) >= thr) {
                        int p = atomicAdd(&CNT[row], 1);
                        if (p < CAP) CAND[row * CAP + p] = (unsigned short)col;
                    }
                    if (fmap(ub[nf][1]) >= thr) {
                        int p = atomicAdd(&CNT[row], 1);
                        if (p < CAP) CAND[row * CAP + p] = (unsigned short)(col + 1);
                    }
                }
            }
        }
        // reset accumulators for next v-tile
        #pragma unroll
        for (int mf = 0; mf < 2; mf++)
            #pragma unroll
            for (int nf = 0; nf < 8; nf++)
                #pragma unroll
                for (int q = 0; q < 4; q++) acc[mf][nf][q] = 0.f;
    }
    __syncthreads();   // all candidate pushes visible before rescore

    // ---- exact fp32 rescore of candidates (warp per row, 16 rows/warp) ----
    for (int rr = 0; rr < 16; rr++) {
        const int row = rr * 8 + w;
        const int r = m0 + row;
        float xr[8];
        const float* xp = g_hflat + (size_t)r * C_DIM;
        #pragma unroll
        for (int i = 0; i < 8; i++) xr[i] = xp[lane + i * 32];

        const int n = CNT[row];
        const bool full = (n > CAP);
        const int total = full ? VOCAB : n;

        float best = -FLT_MAX;
        int bidx = VOCAB;
        for (int j = 0; j < total; j++) {
            const int v = full ? j : (int)CAND[row * CAP + j];
            const float* ev = emb + (size_t)v * C_DIM;
            float p = 0.f;
            #pragma unroll
            for (int i = 0; i < 8; i++) p = fmaf(xr[i], __ldg(&ev[lane + i * 32]), p);
            #pragma unroll
            for (int o = 16; o > 0; o >>= 1) p += __shfl_xor_sync(0xFFFFFFFFu, p, o);
            const float s = p - __ldg(&g_halfnorm[v]);
            if (s > best || (s == best && v < bidx)) { best = s; bidx = v; }
        }
        if (lane == 0) { g_bestscore[r] = best; g_bestidx[r] = bidx; }
    }
}

// ---------------------------------------------------------------------------
// z_q gather (B,C,H,W) + fused indices output
__global__ void gather_kernel(const float* __restrict__ emb, float* __restrict__ out) {
    int bc = blockIdx.x;
    int b = bc >> 8, c = bc & 255;
    int t = threadIdx.x;
    #pragma unroll
    for (int u = 0; u < 4; u++) {
        int sp = t + u * 256;
        int n = b * 1024 + sp;
        int idx = g_bestidx[n];
        out[(size_t)bc * 1024 + sp] = __ldg(&emb[(size_t)idx * C_DIM + c]);
        if (c == 0) out[4194304 + n] = (float)idx;
    }
}

__global__ void loss_kernel(float* __restrict__ out) {
    __shared__ float sm[256];
    int t = threadIdx.x;
    float s1 = 0.f, s2 = 0.f;
    for (int i = t; i < 4096; i += 256)  s1 += g_partial[i];
    for (int i = t; i < N_VEC; i += 256) s2 += g_bestscore[i];
    sm[t] = s1 - 2.f * s2;
    __syncthreads();
    #pragma unroll
    for (int o = 128; o > 0; o >>= 1) {
        if (t < o) sm[t] += sm[t + o];
        __syncthreads();
    }
    if (t == 0) out[4210688] = sm[0] / 4194304.f;
}

// ---------------------------------------------------------------------------
extern "C" void kernel_launch(void* const* d_in, const int* in_sizes, int n_in,
                              void* d_out, int out_size) {
    const float* h   = (const float*)d_in[0];
    const float* emb = (const float*)d_in[1];
    float* out = (float*)d_out;

    static bool attr_set = false;
    if (!attr_set) {
        cudaFuncSetAttribute(pass1_kernel,
                             cudaFuncAttributeMaxDynamicSharedMemorySize, SMEM_P1);
        attr_set = true;
    }

    dim3 tgrid(32, 8, 16), tblk(32, 8);
    prep_h_kernel<<<tgrid, tblk>>>(h);
    prep_emb_kernel<<<VOCAB, 256>>>(emb);
    xnorm_kernel<<<N_VEC / 8, 256>>>();

    pass1_kernel<<<N_VEC / MTILE, 256, SMEM_P1>>>(emb);

    gather_kernel<<<4096, 256>>>(emb, out);
    loss_kernel<<<1, 256>>>(out);
}

// round 12
// speedup vs baseline: 1.2575x; 1.2575x over previous
#include <cuda_runtime.h>
#include <cuda_fp16.h>
#include <cstdint>
#include <cfloat>

#define N_VEC  16384
#define VOCAB  4096
#define C_DIM  256

// rigorous fp16-quantization margin: |s_hat - s_exact| <= MCOEF*||x||*||e|| + SLK
#define MCOEF  1.06e-3f
#define SLK    0.05f

// ---------------------------------------------------------------------------
__device__ float  g_hflat[N_VEC * C_DIM];     // h transposed (N,C) fp32
__device__ __half g_A16[N_VEC * C_DIM];       // fp16 copy
__device__ __half g_B16[VOCAB * C_DIM];       // fp16 codebook
__device__ float  g_halfnorm[VOCAB];          // 0.5*||e||^2 (rescore/loss)
__device__ alignas(16) float2 g_hne[VOCAB];   // (0.5*||e||^2, ||e||) packed
__device__ float  g_xnorm[N_VEC];             // ||x||
__device__ float  g_bestscore[N_VEC];
__device__ int    g_bestidx[N_VEC];
__device__ float  g_partial[4096];

// ---------------------------------------------------------------------------
__device__ __forceinline__ uint32_t smem_u32(const void* p) {
    uint32_t a;
    asm("{ .reg .u64 t; cvta.to.shared.u64 t, %1; cvt.u32.u64 %0, t; }"
        : "=r"(a) : "l"(p));
    return a;
}
__device__ __forceinline__ unsigned fmap(float f) {
    unsigned u = __float_as_uint(f);
    return u ^ ((unsigned)((int)u >> 31) | 0x80000000u);
}
#define CP_ASYNC16(saddr, gptr) \
    asm volatile("cp.async.cg.shared.global [%0], [%1], 16;" \
                 :: "r"(saddr), "l"(gptr) : "memory")
#define CP_COMMIT() asm volatile("cp.async.commit_group;" ::: "memory")
#define CP_WAIT2()  asm volatile("cp.async.wait_group 2;" ::: "memory")
#define CP_WAIT1()  asm volatile("cp.async.wait_group 1;" ::: "memory")
#define CP_WAIT0()  asm volatile("cp.async.wait_group 0;" ::: "memory")

#define PAIR_BAR(id) \
    asm volatile("bar.sync %0, 64;" :: "r"(id) : "memory")

#define MMA16816(c, a, b) \
    asm volatile( \
        "mma.sync.aligned.m16n8k16.row.col.f32.f16.f16.f32 " \
        "{%0,%1,%2,%3}, {%4,%5,%6,%7}, {%8,%9}, {%0,%1,%2,%3};" \
        : "+f"((c)[0]), "+f"((c)[1]), "+f"((c)[2]), "+f"((c)[3]) \
        : "r"((a)[0]), "r"((a)[1]), "r"((a)[2]), "r"((a)[3]), \
          "r"((b)[0]), "r"((b)[1]))

#define LDSM_X4(r0, r1, r2, r3, addr) \
    asm volatile("ldmatrix.sync.aligned.m8n8.x4.shared.b16 {%0,%1,%2,%3}, [%4];" \
                 : "=r"(r0), "=r"(r1), "=r"(r2), "=r"(r3) : "r"(addr))

// ---------------------------------------------------------------------------
// transpose h (B,C,H,W)->(N,C): fp32 + fp16 copies, fused sum(h^2) partial
__global__ void prep_h_kernel(const float* __restrict__ h) {
    __shared__ float tile[32][33];
    __shared__ float rsm[8];
    int b = blockIdx.z, ct = blockIdx.y, st = blockIdx.x;
    int c0 = ct * 32, s0 = st * 32;
    int tx = threadIdx.x, ty = threadIdx.y;
    int t = ty * 32 + tx;

    const float* src = h + ((size_t)b * C_DIM + c0) * 1024 + s0;
    float sq = 0.f;
    #pragma unroll
    for (int i = 0; i < 32; i += 8) {
        float v = src[(size_t)(ty + i) * 1024 + tx];
        tile[ty + i][tx] = v;
        sq = fmaf(v, v, sq);
    }
    __syncthreads();
    size_t rowbase = (size_t)b * 1024 + s0;
    #pragma unroll
    for (int i = 0; i < 32; i += 8) {
        float x = tile[tx][ty + i];
        size_t idx = (rowbase + ty + i) * C_DIM + c0 + tx;
        g_hflat[idx] = x;
        g_A16[idx]   = __float2half_rn(x);
    }
    #pragma unroll
    for (int o = 16; o > 0; o >>= 1) sq += __shfl_down_sync(0xFFFFFFFFu, sq, o);
    if ((t & 31) == 0) rsm[t >> 5] = sq;
    __syncthreads();
    if (t == 0) {
        float tot = 0.f;
        #pragma unroll
        for (int i = 0; i < 8; i++) tot += rsm[i];
        g_partial[(b * 8 + ct) * 32 + st] = tot;
    }
}

__global__ void prep_emb_kernel(const float* __restrict__ emb) {
    int v = blockIdx.x, t = threadIdx.x;
    float x = emb[v * C_DIM + t];
    g_B16[v * C_DIM + t] = __float2half_rn(x);

    float s = x * x;
    __shared__ float sm[8];
    #pragma unroll
    for (int o = 16; o > 0; o >>= 1) s += __shfl_down_sync(0xFFFFFFFFu, s, o);
    if ((t & 31) == 0) sm[t >> 5] = s;
    __syncthreads();
    if (t == 0) {
        float tot = 0.f;
        #pragma unroll
        for (int i = 0; i < 8; i++) tot += sm[i];
        g_halfnorm[v] = 0.5f * tot;
        g_hne[v] = make_float2(0.5f * tot, sqrtf(tot));
    }
}

__global__ void xnorm_kernel() {
    int w = threadIdx.x >> 5, lane = threadIdx.x & 31;
    int r = blockIdx.x * 8 + w;
    const float* xr = g_hflat + (size_t)r * C_DIM;
    float p = 0.f;
    #pragma unroll
    for (int i = 0; i < 8; i++) { float x = xr[lane + i * 32]; p = fmaf(x, x, p); }
    #pragma unroll
    for (int o = 16; o > 0; o >>= 1) p += __shfl_xor_sync(0xFFFFFFFFu, p, o);
    if (lane == 0) g_xnorm[r] = sqrtf(p);
}

// ---------------------------------------------------------------------------
// Fused mma.sync GEMM with warp-pair-private B pipeline:
// NO block barriers in the mainloop — each wn-pair of warps loads its own
// 32-row B slice and syncs with a 64-thread named barrier.
// 256 CTAs (M tile 64) x 256 threads (8 warps: wm=w&1, wn=w>>1).
// Warp tile 32x32. v-tile N=128; K chunks of 64 (4 per v-tile). NC=128.
#define MTILE 64
#define LDA   264        // halfs: row 528B == 16 mod 128 -> LDSM conflict-free
#define LDB   72         // halfs: row 144B == 16 mod 128 -> LDSM conflict-free
#define BSTAGE (128 * LDB * 2)   // 18432 bytes
#define CAP   32
#define NC    128                 // 32 v-tiles x 4 K-chunks
#define OFF_A    0                        // 64*264*2 = 33792
#define OFF_B    33792                    // 4 stages * 18432 = 73728
#define OFF_HNE  107520                   // 2 slots * 128 float2 = 2048
#define OFF_XN   109568                   // 64 floats (+pad)
#define OFF_ML   109824                   // 64 u32 (+pad)
#define OFF_CNT  110080                   // 64 ints (+pad)
#define OFF_CAND 110336                   // 64*32 u16 = 4096
#define SMEM_P1  114432

__global__ __launch_bounds__(256, 2) void pass1_kernel(const float* __restrict__ emb) {
    extern __shared__ char smem[];
    const uint32_t sb = smem_u32(smem);
    float*    XN  = reinterpret_cast<float*>(smem + OFF_XN);
    unsigned* ML  = reinterpret_cast<unsigned*>(smem + OFF_ML);
    int*      CNT = reinterpret_cast<int*>(smem + OFF_CNT);
    unsigned short* CAND = reinterpret_cast<unsigned short*>(smem + OFF_CAND);

    const int tid = threadIdx.x;
    const int w = tid >> 5, lane = tid & 31;
    const int wm = w & 1, wn = w >> 1;
    const int barid = wn + 1;        // named barrier per pair (ids 1..4)
    const int m0 = blockIdx.x * MTILE;
    const int lg = lane >> 2;        // group id 0..7
    const int lq = lane & 3;         // quad id 0..3

    if (tid < 64) {
        XN[tid] = __ldg(&g_xnorm[m0 + tid]);
        ML[tid] = 0u;
        CNT[tid] = 0;
    }

    // ldmatrix lane addresses (bytes)
    const uint32_t aLane = (uint32_t)(((lane & 15) * LDA + (lane >> 4) * 8) * 2);
    const uint32_t aBase0 = sb + OFF_A + (uint32_t)(wm * 32 * LDA * 2) + aLane;
    const uint32_t bLane = (uint32_t)(
        ((((lane & 7) | ((lane >> 4) << 3)) * LDB) + ((lane >> 3) & 1) * 8) * 2);
    const uint32_t bWarp = (uint32_t)(wn * 32 * LDB * 2) + bLane;

    // pair-private B loader: this warp loads 16 rows of the pair's 32-row slice
    const int prow = wn * 32 + wm * 16 + (lane >> 1);   // B row within chunk
    const int pseg = (lane & 1) * 4;                    // 4 of 8 16B-segs per row
    const uint32_t pdst = (uint32_t)(prow * LDB * 2);

    // resident A tile (block-cooperative, own commit group)
    const int lar = tid >> 5, laq = tid & 31;
    #pragma unroll
    for (int i = 0; i < 8; i++) {
        int r = lar + i * 8;
        CP_ASYNC16(sb + OFF_A + (uint32_t)(r * LDA * 2 + laq * 16),
                   g_A16 + (size_t)(m0 + r) * C_DIM + laq * 8);
    }
    CP_COMMIT();

    // prefetch chunk c (pair slice only): vt = c>>2, kc = c&3
    #define PREFETCH(c) do {                                                     \
        const int _vt = (c) >> 2, _kc = (c) & 3;                                 \
        const uint32_t _dst = sb + OFF_B + (uint32_t)(((c) & 3) * BSTAGE) + pdst; \
        const __half* _src = g_B16 + (size_t)(_vt * 128 + prow) * C_DIM + _kc * 64; \
        _Pragma("unroll")                                                        \
        for (int _j = 0; _j < 4; _j++)                                           \
            CP_ASYNC16(_dst + (uint32_t)((pseg + _j) * 16), _src + (pseg + _j) * 8); \
        if (_kc == 0 && wm == 0 && lane < 16) {                                  \
            CP_ASYNC16(sb + OFF_HNE + (uint32_t)((_vt & 1) * 1024 + (wn * 32 + lane * 2) * 8), \
                       g_hne + _vt * 128 + wn * 32 + lane * 2);                  \
        }                                                                        \
        CP_COMMIT();                                                             \
    } while (0)

    PREFETCH(0);
    PREFETCH(1);
    PREFETCH(2);
    CP_WAIT2();        // A group + chunk 0 complete (per thread)
    __syncthreads();   // ONLY block barrier before the mainloop:
                       // A tile + chunk 0 + XN/ML/CNT visible to all warps

    float acc[2][4][4];

    #pragma unroll 2
    for (int i = 0; i < NC; i++) {
        // own-group wait: chunk i complete for this thread
        if (i < NC - 2)       CP_WAIT2();
        else if (i == NC - 2) CP_WAIT1();
        else                  CP_WAIT0();
        // pair barrier: partner's half of chunk i visible; partner finished
        // its iter i-1 reads of stage (i+3)&3 -> safe to overwrite below
        PAIR_BAR(barid);

        if (i + 3 < NC) PREFETCH(i + 3);

        const int kc = i & 3;
        const int vt = i >> 2;

        if (kc == 0) {
            #pragma unroll
            for (int mf = 0; mf < 2; mf++)
                #pragma unroll
                for (int nf = 0; nf < 4; nf++)
                    #pragma unroll
                    for (int q = 0; q < 4; q++) acc[mf][nf][q] = 0.f;
        }

        const uint32_t bStage = sb + OFF_B + (uint32_t)((i & 3) * BSTAGE) + bWarp;
        const uint32_t aK = (uint32_t)(kc * 64 * 2);

        #pragma unroll
        for (int ks = 0; ks < 4; ks++) {
            uint32_t a[2][4], b[4][2];
            const uint32_t ka = aK + (uint32_t)(ks * 32);
            const uint32_t kb = (uint32_t)(ks * 32);
            LDSM_X4(a[0][0], a[0][1], a[0][2], a[0][3], aBase0 + ka);
            LDSM_X4(a[1][0], a[1][1], a[1][2], a[1][3],
                    aBase0 + (uint32_t)(16 * LDA * 2) + ka);
            LDSM_X4(b[0][0], b[0][1], b[1][0], b[1][1], bStage + kb);
            LDSM_X4(b[2][0], b[2][1], b[3][0], b[3][1],
                    bStage + (uint32_t)(16 * LDB * 2) + kb);
            #pragma unroll
            for (int mf = 0; mf < 2; mf++)
                #pragma unroll
                for (int nf = 0; nf < 4; nf++)
                    MMA16816(acc[mf][nf], a[mf], b[nf]);
        }

        if (kc == 3) {
            // ---- register epilogue for v-tile [vt*128, +128); no barriers ----
            const float* HNE = reinterpret_cast<const float*>(
                smem + OFF_HNE + (vt & 1) * 1024);
            const int v0 = vt << 7;
            const int rbase = wm * 32 + lg;
            #pragma unroll
            for (int mf = 0; mf < 2; mf++) {
                #pragma unroll
                for (int hh = 0; hh < 2; hh++) {
                    const int row = rbase + mf * 16 + hh * 8;
                    const float mx = MCOEF * XN[row];
                    float lowmax = -FLT_MAX;
                    float ub[4][2];
                    #pragma unroll
                    for (int nf = 0; nf < 4; nf++) {
                        const int col = wn * 32 + nf * 8 + lq * 2;
                        float4 q4 = *reinterpret_cast<const float4*>(HNE + col * 2);
                        float s0 = acc[mf][nf][2 * hh]     - q4.x;
                        float s1 = acc[mf][nf][2 * hh + 1] - q4.z;
                        float me0 = fmaf(mx, q4.y, SLK);
                        float me1 = fmaf(mx, q4.w, SLK);
                        lowmax = fmaxf(lowmax, fmaxf(s0 - me0, s1 - me1));
                        ub[nf][0] = s0 + me0;
                        ub[nf][1] = s1 + me1;
                    }
                    atomicMax(&ML[row], fmap(lowmax));
                    // stale-lower threshold is still a valid lower bound ->
                    // candidate set stays a superset of the true argmax
                    const unsigned thr = ML[row];
                    #pragma unroll
                    for (int nf = 0; nf < 4; nf++) {
                        const int col = v0 + wn * 32 + nf * 8 + lq * 2;
                        if (fmap(ub[nf][0]) >= thr) {
                            int p = atomicAdd(&CNT[row], 1);
                            if (p < CAP) CAND[row * CAP + p] = (unsigned short)col;
                        }
                        if (fmap(ub[nf][1]) >= thr) {
                            int p = atomicAdd(&CNT[row], 1);
                            if (p < CAP) CAND[row * CAP + p] = (unsigned short)(col + 1);
                        }
                    }
                }
            }
        }
    }
    __syncthreads();   // all pairs' candidate pushes visible before rescore

    // ---- exact fp32 rescore of candidates (warp per row) ----
    for (int rr = 0; rr < 8; rr++) {
        const int row = rr * 8 + w;
        const int r = m0 + row;
        float xr[8];
        const float* xp = g_hflat + (size_t)r * C_DIM;
        #pragma unroll
        for (int i = 0; i < 8; i++) xr[i] = xp[lane + i * 32];

        const int n = CNT[row];
        const bool full = (n > CAP);
        const int total = full ? VOCAB : n;

        float best = -FLT_MAX;
        int bidx = VOCAB;
        for (int j = 0; j < total; j++) {
            const int v = full ? j : (int)CAND[row * CAP + j];
            const float* ev = emb + (size_t)v * C_DIM;
            float p = 0.f;
            #pragma unroll
            for (int i = 0; i < 8; i++) p = fmaf(xr[i], __ldg(&ev[lane + i * 32]), p);
            #pragma unroll
            for (int o = 16; o > 0; o >>= 1) p += __shfl_xor_sync(0xFFFFFFFFu, p, o);
            const float s = p - __ldg(&g_halfnorm[v]);
            if (s > best || (s == best && v < bidx)) { best = s; bidx = v; }
        }
        if (lane == 0) { g_bestscore[r] = best; g_bestidx[r] = bidx; }
    }
}

// ---------------------------------------------------------------------------
// z_q gather (B,C,H,W) + fused indices output
__global__ void gather_kernel(const float* __restrict__ emb, float* __restrict__ out) {
    int bc = blockIdx.x;
    int b = bc >> 8, c = bc & 255;
    int t = threadIdx.x;
    #pragma unroll
    for (int u = 0; u < 4; u++) {
        int sp = t + u * 256;
        int n = b * 1024 + sp;
        int idx = g_bestidx[n];
        out[(size_t)bc * 1024 + sp] = __ldg(&emb[(size_t)idx * C_DIM + c]);
        if (c == 0) out[4194304 + n] = (float)idx;
    }
}

__global__ void loss_kernel(float* __restrict__ out) {
    __shared__ float sm[256];
    int t = threadIdx.x;
    float s1 = 0.f, s2 = 0.f;
    for (int i = t; i < 4096; i += 256)  s1 += g_partial[i];
    for (int i = t; i < N_VEC; i += 256) s2 += g_bestscore[i];
    sm[t] = s1 - 2.f * s2;
    __syncthreads();
    #pragma unroll
    for (int o = 128; o > 0; o >>= 1) {
        if (t < o) sm[t] += sm[t + o];
        __syncthreads();
    }
    if (t == 0) out[4210688] = sm[0] / 4194304.f;
}

// ---------------------------------------------------------------------------
extern "C" void kernel_launch(void* const* d_in, const int* in_sizes, int n_in,
                              void* d_out, int out_size) {
    const float* h   = (const float*)d_in[0];
    const float* emb = (const float*)d_in[1];
    float* out = (float*)d_out;

    static bool attr_set = false;
    if (!attr_set) {
        cudaFuncSetAttribute(pass1_kernel,
                             cudaFuncAttributeMaxDynamicSharedMemorySize, SMEM_P1);
        attr_set = true;
    }

    dim3 tgrid(32, 8, 16), tblk(32, 8);
    prep_h_kernel<<<tgrid, tblk>>>(h);
    prep_emb_kernel<<<VOCAB, 256>>>(emb);
    xnorm_kernel<<<N_VEC / 8, 256>>>();

    pass1_kernel<<<N_VEC / MTILE, 256, SMEM_P1>>>(emb);

    gather_kernel<<<4096, 256>>>(emb, out);
    loss_kernel<<<1, 256>>>(out);
}